// round 13
// baseline (speedup 1.0000x reference)
#include <cuda_runtime.h>
#include <cuda_bf16.h>
#include <math.h>

#define NTOK 1024
#define CQ   768
#define CZ   128
#define NH   16
#define HD   48

// ---------------- scratch (static device memory) ----------------
__device__ float g_q   [NTOK * CQ];
__device__ float g_k   [NTOK * CQ];
__device__ float g_v   [NTOK * CQ];
__device__ float g_gate[NTOK * CQ];
__device__ float g_og  [NTOK * CQ];
__device__ float g_sc  [(size_t)NTOK * NH * NTOK];   // pair+mask bias, layout [i][h][j]
__device__ float g_wp  [CZ * NH];
__device__ float g_wpT [NH * 132];
__device__ float g_Wh  [NH];
__device__ float g_ch  [NH];
__device__ float g_mu  [NTOK];
__device__ float g_rs  [NTOK];

// ---------------- helpers ----------------
__device__ __forceinline__ unsigned f2tf(float x) {
    unsigned u; asm("cvt.rna.tf32.f32 %0, %1;" : "=r"(u) : "f"(x)); return u;
}
__device__ __forceinline__ float tf32f(float x) { return __uint_as_float(f2tf(x)); }
__device__ __forceinline__ unsigned su(float x) { return __float_as_uint(x); }

// pack (even k -> low half, odd k -> high half), hi/lo bf16 split
__device__ __forceinline__ void bfsplit2(float e, float o, unsigned& hw, unsigned& lw) {
    __nv_bfloat162 h2, l2;
    h2.x = __float2bfloat16_rn(e);
    h2.y = __float2bfloat16_rn(o);
    l2.x = __float2bfloat16_rn(e - __bfloat162float(h2.x));
    l2.y = __float2bfloat16_rn(o - __bfloat162float(h2.y));
    hw = *(unsigned*)&h2;
    lw = *(unsigned*)&l2;
}

__device__ __forceinline__ void ldsm_x4(unsigned& r0, unsigned& r1, unsigned& r2, unsigned& r3,
                                        const unsigned* p) {
    unsigned addr = (unsigned)__cvta_generic_to_shared(p);
    asm volatile("ldmatrix.sync.aligned.m8n8.x4.shared.b16 {%0,%1,%2,%3}, [%4];"
                 : "=r"(r0), "=r"(r1), "=r"(r2), "=r"(r3) : "r"(addr));
}

#define MMA_TF32(c, a, b0_, b1_)                                              \
    asm volatile("mma.sync.aligned.m16n8k8.row.col.f32.tf32.tf32.f32 "        \
                 "{%0,%1,%2,%3}, {%4,%5,%6,%7}, {%8,%9}, {%0,%1,%2,%3};"      \
                 : "+f"(c[0]), "+f"(c[1]), "+f"(c[2]), "+f"(c[3])             \
                 : "r"(a[0]), "r"(a[1]), "r"(a[2]), "r"(a[3]),                \
                   "r"(b0_), "r"(b1_));

#define MMA_BF16(c, a, b0_, b1_)                                              \
    asm volatile("mma.sync.aligned.m16n8k16.row.col.f32.bf16.bf16.f32 "       \
                 "{%0,%1,%2,%3}, {%4,%5,%6,%7}, {%8,%9}, {%0,%1,%2,%3};"      \
                 : "+f"(c[0]), "+f"(c[1]), "+f"(c[2]), "+f"(c[3])             \
                 : "r"(a[0]), "r"(a[1]), "r"(a[2]), "r"(a[3]),                \
                   "r"(b0_), "r"(b1_));

// ---------------- per-row LN stats of a ----------------
__global__ void __launch_bounds__(256) a_stats_kernel(const float* __restrict__ a) {
    int row = blockIdx.x;
    int tid = threadIdx.x;
    const float* x = a + (size_t)row * CQ;
    __shared__ float red[256];

    float xv[3];
    float s = 0.f;
#pragma unroll
    for (int k = 0; k < 3; k++) { xv[k] = x[tid + k * 256]; s += xv[k]; }
    red[tid] = s; __syncthreads();
    for (int st = 128; st > 0; st >>= 1) { if (tid < st) red[tid] += red[tid + st]; __syncthreads(); }
    float mu = red[0] * (1.f / CQ);
    __syncthreads();

    float s2 = 0.f;
#pragma unroll
    for (int k = 0; k < 3; k++) { float d = xv[k] - mu; s2 += d * d; }
    red[tid] = s2; __syncthreads();
    for (int st = 128; st > 0; st >>= 1) { if (tid < st) red[tid] += red[tid + st]; __syncthreads(); }
    if (tid == 0) {
        g_mu[row] = mu;
        g_rs[row] = rsqrtf(red[0] * (1.f / CQ) + 1e-5f);
    }
}

// ---------------- pair-bias precompute ----------------
__global__ void prep_kernel(const float* __restrict__ gz,
                            const float* __restrict__ bz,
                            const float* __restrict__ wz) {
    int tid = threadIdx.x;       // 128
    float gzc = gz[tid];
    for (int h = 0; h < NH; h++) {
        float w = gzc * wz[tid * NH + h];
        g_wp[tid * NH + h] = w;
        g_wpT[h * 132 + tid] = tf32f(w);
    }
    __syncthreads();
    if (tid < NH) {
        float W = 0.f, C = 0.f;
        for (int c = 0; c < CZ; c++) {
            W += g_wp[c * NH + tid];
            C += bz[c] * wz[c * NH + tid];
        }
        g_Wh[tid] = W;
        g_ch[tid] = C;
    }
}

// ---------------- pair bias via tensor cores (unchanged, proven) ----------------
__global__ void __launch_bounds__(256) pair_mma(const float* __restrict__ z,
                                                const float* __restrict__ mask) {
    extern __shared__ float psm[];
    float* zs  = psm;                     // 128*132
    float* wpt = zs + 128 * 132;          // 16*132
    float* sb  = wpt + 16 * 132;          // 16*132
    float* mus = sb + 16 * 132;           // 128
    float* rss = mus + 128;               // 128

    int i  = blockIdx.y;
    int j0 = blockIdx.x * 128;
    int tid = threadIdx.x, lane = tid & 31, w = tid >> 5;
    int g = lane >> 2, t = lane & 3;

    for (int e = tid; e < NH * 132; e += 256) wpt[e] = g_wpT[e];

    int row = tid >> 1, c0 = (tid & 1) * 64;
    const float* zrow = z + ((size_t)i * NTOK + j0 + row) * CZ + c0;
    float s1 = 0.f, s2 = 0.f;
#pragma unroll
    for (int q = 0; q < 16; q++) {
        float4 v = *(const float4*)&zrow[q * 4];
        s1 += v.x + v.y + v.z + v.w;
        s2 += v.x * v.x + v.y * v.y + v.z * v.z + v.w * v.w;
        float4 hv = make_float4(tf32f(v.x), tf32f(v.y), tf32f(v.z), tf32f(v.w));
        *(float4*)&zs[row * 132 + c0 + q * 4] = hv;
    }
    s1 += __shfl_xor_sync(0xffffffffu, s1, 1);
    s2 += __shfl_xor_sync(0xffffffffu, s2, 1);
    float mu = s1 * (1.f / CZ);
    float var = s2 * (1.f / CZ) - mu * mu;
    float rs = rsqrtf(var + 1e-5f);
    if ((tid & 1) == 0) { mus[row] = mu; rss[row] = rs; }
    __syncthreads();

    int wr = w * 16;
    float c[2][4] = {};
#pragma unroll
    for (int ks = 0; ks < 16; ks++) {
        int kk = ks * 8;
        unsigned a[4];
        a[0] = su(zs[(wr + g) * 132 + kk + t]);
        a[1] = su(zs[(wr + g + 8) * 132 + kk + t]);
        a[2] = su(zs[(wr + g) * 132 + kk + t + 4]);
        a[3] = su(zs[(wr + g + 8) * 132 + kk + t + 4]);
#pragma unroll
        for (int nt = 0; nt < 2; nt++) {
            unsigned b0 = su(wpt[(nt * 8 + g) * 132 + kk + t]);
            unsigned b1 = su(wpt[(nt * 8 + g) * 132 + kk + t + 4]);
            MMA_TF32(c[nt], a, b0, b1);
        }
    }

    float muA = mus[wr + g], rsA = rss[wr + g];
    float muB = mus[wr + g + 8], rsB = rss[wr + g + 8];
#pragma unroll
    for (int nt = 0; nt < 2; nt++) {
#pragma unroll
        for (int cc = 0; cc < 2; cc++) {
            int h = nt * 8 + 2 * t + cc;
            float W = g_Wh[h], C0 = g_ch[h];
            sb[h * 132 + wr + g]     = rsA * (c[nt][cc]     - muA * W) + C0;
            sb[h * 132 + wr + g + 8] = rsB * (c[nt][cc + 2] - muB * W) + C0;
        }
    }
    __syncthreads();

    float mi = mask[i];
#pragma unroll
    for (int e = tid; e < NH * 128; e += 256) {
        int h = e >> 7, j = e & 127;
        float mb = 1.0e9f * (mi * mask[j0 + j] - 1.f);
        g_sc[((size_t)i * NH + h) * NTOK + j0 + j] = sb[h * 132 + j] + mb;
    }
}

// ========== 3xBF16-split GEMM, 128x64 tile, BK=16, ldmatrix fragment loads ==========
// A smem: [m][12] words (word = bf16x2 of k-pair), m=0..127, p=0..7 used
// B smem: [n][12] words, n=0..63, p=0..7 used
#define ASTR 12
#define BSTR 12

template <int LN_A>
__device__ __forceinline__ void gemm_core_bf(const float* __restrict__ A,
                                             const float* __restrict__ B,
                                             const float* __restrict__ gw,
                                             const float* __restrict__ bw,
                                             float c[2][4][4],
                                             unsigned* sAh, unsigned* sAl,
                                             unsigned* sBh, unsigned* sBl) {
    int tid  = threadIdx.x;
    int lane = tid & 31, w = tid >> 5;
    int wm = w & 3, wn = w >> 2;
    int m0 = blockIdx.y * 128, n0 = blockIdx.x * 64;
    int arow = tid >> 1, akb = (tid & 1) * 8;
    int bp = tid >> 5, bn2 = (tid & 31) * 2;

    // ldmatrix per-lane addresses (fixed across chunks)
    int lr = lane & 15, lc = (lane >> 4) * 4;
    const unsigned* aH0 = sAh + (wm * 32 + 0 * 16 + lr) * ASTR + lc;
    const unsigned* aH1 = sAh + (wm * 32 + 1 * 16 + lr) * ASTR + lc;
    const unsigned* aL0 = sAl + (wm * 32 + 0 * 16 + lr) * ASTR + lc;
    const unsigned* aL1 = sAl + (wm * 32 + 1 * 16 + lr) * ASTR + lc;
    const unsigned* bH0 = sBh + (wn * 32 + 0 * 16 + lr) * BSTR + lc;
    const unsigned* bH1 = sBh + (wn * 32 + 1 * 16 + lr) * BSTR + lc;
    const unsigned* bL0 = sBl + (wn * 32 + 0 * 16 + lr) * BSTR + lc;
    const unsigned* bL1 = sBl + (wn * 32 + 1 * 16 + lr) * BSTR + lc;

    float mu = 0.f, rs = 1.f;
    if (LN_A) { mu = g_mu[m0 + arow]; rs = g_rs[m0 + arow]; }
    const float* Arow = A + (size_t)(m0 + arow) * CQ;

    for (int k0 = 0; k0 < CQ; k0 += 16) {
        __syncthreads();
        // ---- A tile: 8 consecutive k per thread -> 4 packed words, STS.128 ----
        {
            float4 v0 = *(const float4*)&Arow[k0 + akb];
            float4 v1 = *(const float4*)&Arow[k0 + akb + 4];
            float xs[8] = {v0.x, v0.y, v0.z, v0.w, v1.x, v1.y, v1.z, v1.w};
            if (LN_A) {
#pragma unroll
                for (int q = 0; q < 8; q++)
                    xs[q] = (xs[q] - mu) * rs * gw[k0 + akb + q] + bw[k0 + akb + q];
            }
            uint4 hw, lw;
            bfsplit2(xs[0], xs[1], hw.x, lw.x);
            bfsplit2(xs[2], xs[3], hw.y, lw.y);
            bfsplit2(xs[4], xs[5], hw.z, lw.z);
            bfsplit2(xs[6], xs[7], hw.w, lw.w);
            int p0 = akb >> 1;   // 0 or 4
            *(uint4*)&sAh[arow * ASTR + p0] = hw;
            *(uint4*)&sAl[arow * ASTR + p0] = lw;
        }
        // ---- B tile: thread loads 2 n for 2 consecutive k rows ----
        {
            const float* Bp = &B[(size_t)(k0 + 2 * bp) * CQ + n0 + bn2];
            float2 r0 = *(const float2*)Bp;
            float2 r1 = *(const float2*)(Bp + CQ);
            unsigned hw0, lw0, hw1, lw1;
            bfsplit2(r0.x, r1.x, hw0, lw0);
            bfsplit2(r0.y, r1.y, hw1, lw1);
            sBh[bn2 * BSTR + bp]       = hw0;
            sBh[(bn2 + 1) * BSTR + bp] = hw1;
            sBl[bn2 * BSTR + bp]       = lw0;
            sBl[(bn2 + 1) * BSTR + bp] = lw1;
        }
        __syncthreads();

        // ---- fragments via ldmatrix ----
        unsigned Ah[2][4], Al[2][4], BH[2][4], BL[2][4];
        ldsm_x4(Ah[0][0], Ah[0][1], Ah[0][2], Ah[0][3], aH0);
        ldsm_x4(Ah[1][0], Ah[1][1], Ah[1][2], Ah[1][3], aH1);
        ldsm_x4(Al[0][0], Al[0][1], Al[0][2], Al[0][3], aL0);
        ldsm_x4(Al[1][0], Al[1][1], Al[1][2], Al[1][3], aL1);
        // B x4 regs: {b0 of nt-even, b0 of nt-odd, b1 of nt-even, b1 of nt-odd}
        ldsm_x4(BH[0][0], BH[0][1], BH[0][2], BH[0][3], bH0);
        ldsm_x4(BH[1][0], BH[1][1], BH[1][2], BH[1][3], bH1);
        ldsm_x4(BL[0][0], BL[0][1], BL[0][2], BL[0][3], bL0);
        ldsm_x4(BL[1][0], BL[1][1], BL[1][2], BL[1][3], bL1);

#pragma unroll
        for (int mt = 0; mt < 2; mt++)
#pragma unroll
            for (int np = 0; np < 2; np++) {
                // nt even (n offset np*16 + 0)
                MMA_BF16(c[mt][np * 2 + 0], Ah[mt], BH[np][0], BH[np][2]);
                MMA_BF16(c[mt][np * 2 + 0], Ah[mt], BL[np][0], BL[np][2]);
                MMA_BF16(c[mt][np * 2 + 0], Al[mt], BH[np][0], BH[np][2]);
                // nt odd (n offset np*16 + 8)
                MMA_BF16(c[mt][np * 2 + 1], Ah[mt], BH[np][1], BH[np][3]);
                MMA_BF16(c[mt][np * 2 + 1], Ah[mt], BL[np][1], BL[np][3]);
                MMA_BF16(c[mt][np * 2 + 1], Al[mt], BH[np][1], BH[np][3]);
            }
    }
}

#define GEMM_BF_SMEM                                                          \
    __shared__ unsigned sAh[128 * ASTR], sAl[128 * ASTR];                     \
    __shared__ unsigned sBh[64 * BSTR],  sBl[64 * BSTR];

// fused Q/K/V/Gate projections (LN applied to A on the fly)
__global__ void __launch_bounds__(256) qkvg_mma(const float* __restrict__ A,
                                                const float* __restrict__ gw,
                                                const float* __restrict__ bw,
                                                const float* __restrict__ wq,
                                                const float* __restrict__ wk,
                                                const float* __restrict__ wv,
                                                const float* __restrict__ wg,
                                                const float* __restrict__ bg,
                                                float qscale) {
    GEMM_BF_SMEM
    int zi = blockIdx.z;
    const float* B = (zi == 0) ? wq : (zi == 1) ? wk : (zi == 2) ? wv : wg;
    float* O = (zi == 0) ? g_q : (zi == 1) ? g_k : (zi == 2) ? g_v : g_gate;

    float c[2][4][4] = {};
    gemm_core_bf<1>(A, B, gw, bw, c, sAh, sAl, sBh, sBl);

    int lane = threadIdx.x & 31, w = threadIdx.x >> 5;
    int wm = w & 3, wn = w >> 2;
    int g = lane >> 2, t = lane & 3;
    int m0 = blockIdx.y * 128, n0 = blockIdx.x * 64;
#pragma unroll
    for (int mt = 0; mt < 2; mt++) {
        int r0 = m0 + wm * 32 + mt * 16 + g;
#pragma unroll
        for (int nt = 0; nt < 4; nt++) {
            int col = n0 + wn * 32 + nt * 8 + 2 * t;
            float v0 = c[mt][nt][0], v1 = c[mt][nt][1];
            float v2 = c[mt][nt][2], v3 = c[mt][nt][3];
            if (zi == 0) { v0 *= qscale; v1 *= qscale; v2 *= qscale; v3 *= qscale; }
            if (zi == 3) {
                float2 bb = *(const float2*)&bg[col];
                v0 = 1.f / (1.f + __expf(-(v0 + bb.x)));
                v1 = 1.f / (1.f + __expf(-(v1 + bb.y)));
                v2 = 1.f / (1.f + __expf(-(v2 + bb.x)));
                v3 = 1.f / (1.f + __expf(-(v3 + bb.y)));
            }
            *(float2*)&O[(size_t)r0 * CQ + col]       = make_float2(v0, v1);
            *(float2*)&O[(size_t)(r0 + 8) * CQ + col] = make_float2(v2, v3);
        }
    }
}

// out projection
__global__ void __launch_bounds__(256) out_mma(const float* __restrict__ A,
                                               const float* __restrict__ B,
                                               float* __restrict__ C,
                                               const float* __restrict__ bias) {
    GEMM_BF_SMEM
    float c[2][4][4] = {};
    gemm_core_bf<0>(A, B, (const float*)0, (const float*)0, c, sAh, sAl, sBh, sBl);

    int lane = threadIdx.x & 31, w = threadIdx.x >> 5;
    int wm = w & 3, wn = w >> 2;
    int g = lane >> 2, t = lane & 3;
    int m0 = blockIdx.y * 128, n0 = blockIdx.x * 64;
#pragma unroll
    for (int mt = 0; mt < 2; mt++) {
        int r0 = m0 + wm * 32 + mt * 16 + g;
#pragma unroll
        for (int nt = 0; nt < 4; nt++) {
            int col = n0 + wn * 32 + nt * 8 + 2 * t;
            float2 bb = *(const float2*)&bias[col];
            *(float2*)&C[(size_t)r0 * CQ + col] =
                make_float2(c[mt][nt][0] + bb.x, c[mt][nt][1] + bb.y);
            *(float2*)&C[(size_t)(r0 + 8) * CQ + col] =
                make_float2(c[mt][nt][2] + bb.x, c[mt][nt][3] + bb.y);
        }
    }
}

// ================= flash attention: 64 q-rows x 2 heads per block, 256 thr =================
// smem: Ks[2][64*68] | Vs[2][64*72] | Ps[8][16*68]; bias loaded direct to fragments
__global__ void __launch_bounds__(256) flash_mma() {
    extern __shared__ float fsm[];

    int tid = threadIdx.x, w = tid >> 5, lane = tid & 31;
    int hh = w >> 2, wl = w & 3;
    int g = lane >> 2, t = lane & 3;

    float* Ks = fsm + hh * 4352;
    float* Vs = fsm + 8704 + hh * 4608;
    float* Pw = fsm + 8704 + 9216 + w * 1088;

    int h  = blockIdx.y * 2 + hh;
    int i0 = blockIdx.x * 64;
    int irow = i0 + wl * 16 + g;

    unsigned aq[6][4];
    {
        const float* q0 = g_q + (size_t)irow * CQ + h * HD;
        const float* q8 = q0 + 8 * CQ;
#pragma unroll
        for (int ks = 0; ks < 6; ks++) {
            aq[ks][0] = f2tf(q0[ks * 8 + t]);
            aq[ks][1] = f2tf(q8[ks * 8 + t]);
            aq[ks][2] = f2tf(q0[ks * 8 + t + 4]);
            aq[ks][3] = f2tf(q8[ks * 8 + t + 4]);
        }
    }

    const float* scA = g_sc + ((size_t)irow * NH + h) * NTOK;
    const float* scB = scA + (size_t)8 * NH * NTOK;

    float o[6][4] = {};
    float mrunA = -1e30f, mrunB = -1e30f, lA = 0.f, lB = 0.f;

    for (int jt = 0; jt < 16; jt++) {
        int j0 = jt * 64;
        __syncthreads();

        float s[8][4];
#pragma unroll
        for (int nt = 0; nt < 8; nt++) {
            float2 bA = *(const float2*)&scA[j0 + nt * 8 + 2 * t];
            float2 bB = *(const float2*)&scB[j0 + nt * 8 + 2 * t];
            s[nt][0] = bA.x; s[nt][1] = bA.y; s[nt][2] = bB.x; s[nt][3] = bB.y;
        }

#pragma unroll
        for (int e = tid; e < 1536; e += 256) {
            int hd2 = (e >= 768);
            int e2 = e - hd2 * 768;
            int r = e2 / 12, cc = (e2 % 12) * 4;
            int hl = blockIdx.y * 2 + hd2;
            float* Kd = fsm + hd2 * 4352;
            float* Vd = fsm + 8704 + hd2 * 4608;
            float4 kv = *(const float4*)&g_k[(size_t)(j0 + r) * CQ + hl * HD + cc];
            Kd[r * 68 + cc + 0] = tf32f(kv.x); Kd[r * 68 + cc + 1] = tf32f(kv.y);
            Kd[r * 68 + cc + 2] = tf32f(kv.z); Kd[r * 68 + cc + 3] = tf32f(kv.w);
            float4 vv = *(const float4*)&g_v[(size_t)(j0 + r) * CQ + hl * HD + cc];
            Vd[r * 72 + cc + 0] = tf32f(vv.x); Vd[r * 72 + cc + 1] = tf32f(vv.y);
            Vd[r * 72 + cc + 2] = tf32f(vv.z); Vd[r * 72 + cc + 3] = tf32f(vv.w);
        }
        __syncthreads();

#pragma unroll
        for (int ks = 0; ks < 6; ks++) {
#pragma unroll
            for (int nt = 0; nt < 8; nt++) {
                unsigned b0 = su(Ks[(nt * 8 + g) * 68 + ks * 8 + t]);
                unsigned b1 = su(Ks[(nt * 8 + g) * 68 + ks * 8 + t + 4]);
                MMA_TF32(s[nt], aq[ks], b0, b1);
            }
        }

        float mA = -1e30f, mB = -1e30f;
#pragma unroll
        for (int nt = 0; nt < 8; nt++) {
            mA = fmaxf(mA, fmaxf(s[nt][0], s[nt][1]));
            mB = fmaxf(mB, fmaxf(s[nt][2], s[nt][3]));
        }
#pragma unroll
        for (int oo = 1; oo <= 2; oo <<= 1) {
            mA = fmaxf(mA, __shfl_xor_sync(0xffffffffu, mA, oo));
            mB = fmaxf(mB, __shfl_xor_sync(0xffffffffu, mB, oo));
        }
        float mnA = fmaxf(mrunA, mA), mnB = fmaxf(mrunB, mB);
        float alA = __expf(mrunA - mnA), alB = __expf(mrunB - mnB);
        mrunA = mnA; mrunB = mnB;

        float sumA = 0.f, sumB = 0.f;
#pragma unroll
        for (int nt = 0; nt < 8; nt++) {
            s[nt][0] = __expf(s[nt][0] - mnA); s[nt][1] = __expf(s[nt][1] - mnA);
            s[nt][2] = __expf(s[nt][2] - mnB); s[nt][3] = __expf(s[nt][3] - mnB);
            sumA += s[nt][0] + s[nt][1];
            sumB += s[nt][2] + s[nt][3];
        }
#pragma unroll
        for (int oo = 1; oo <= 2; oo <<= 1) {
            sumA += __shfl_xor_sync(0xffffffffu, sumA, oo);
            sumB += __shfl_xor_sync(0xffffffffu, sumB, oo);
        }
        lA = lA * alA + sumA;
        lB = lB * alB + sumB;
#pragma unroll
        for (int nd = 0; nd < 6; nd++) {
            o[nd][0] *= alA; o[nd][1] *= alA;
            o[nd][2] *= alB; o[nd][3] *= alB;
        }

#pragma unroll
        for (int nt = 0; nt < 8; nt++) {
            *(float2*)&Pw[g * 68 + nt * 8 + 2 * t]       = make_float2(tf32f(s[nt][0]), tf32f(s[nt][1]));
            *(float2*)&Pw[(g + 8) * 68 + nt * 8 + 2 * t] = make_float2(tf32f(s[nt][2]), tf32f(s[nt][3]));
        }
        __syncwarp();

#pragma unroll
        for (int ks = 0; ks < 8; ks++) {
            unsigned pa[4];
            pa[0] = su(Pw[g * 68 + ks * 8 + t]);
            pa[1] = su(Pw[(g + 8) * 68 + ks * 8 + t]);
            pa[2] = su(Pw[g * 68 + ks * 8 + t + 4]);
            pa[3] = su(Pw[(g + 8) * 68 + ks * 8 + t + 4]);
#pragma unroll
            for (int nd = 0; nd < 6; nd++) {
                unsigned b0 = su(Vs[(ks * 8 + t) * 72 + nd * 8 + g]);
                unsigned b1 = su(Vs[(ks * 8 + t + 4) * 72 + nd * 8 + g]);
                MMA_TF32(o[nd], pa, b0, b1);
            }
        }
    }

    float iA = 1.f / lA, iB = 1.f / lB;
#pragma unroll
    for (int nd = 0; nd < 6; nd++) {
        int col = h * HD + nd * 8 + 2 * t;
        size_t iAx = (size_t)irow * CQ + col;
        size_t iBx = (size_t)(irow + 8) * CQ + col;
        float2 ga = *(const float2*)&g_gate[iAx];
        float2 gb = *(const float2*)&g_gate[iBx];
        *(float2*)&g_og[iAx] = make_float2(o[nd][0] * iA * ga.x, o[nd][1] * iA * ga.y);
        *(float2*)&g_og[iBx] = make_float2(o[nd][2] * iB * gb.x, o[nd][3] * iB * gb.y);
    }
}

// ------------------------------- launch -------------------------------
#define PB_SMEM ((128 * 132 + 16 * 132 + 16 * 132 + 256) * 4)
#define FL_SMEM ((2 * 4352 + 2 * 4608 + 8 * 1088) * 4)

extern "C" void kernel_launch(void* const* d_in, const int* in_sizes, int n_in,
                              void* d_out, int out_size) {
    const float* a    = (const float*)d_in[0];
    const float* z    = (const float*)d_in[1];
    const float* mask = (const float*)d_in[2];
    const float* ga   = (const float*)d_in[3];
    const float* ba   = (const float*)d_in[4];
    const float* gz   = (const float*)d_in[5];
    const float* bz   = (const float*)d_in[6];
    const float* wz   = (const float*)d_in[7];
    const float* wq   = (const float*)d_in[8];
    const float* wk   = (const float*)d_in[9];
    const float* wv   = (const float*)d_in[10];
    const float* wg   = (const float*)d_in[11];
    const float* bg   = (const float*)d_in[12];
    const float* wo   = (const float*)d_in[13];
    const float* bo   = (const float*)d_in[14];
    float* out = (float*)d_out;

    float *p_og;
    cudaGetSymbolAddress((void**)&p_og, g_og);

    static int init_done = 0;
    if (!init_done) {
        cudaFuncSetAttribute(flash_mma, cudaFuncAttributeMaxDynamicSharedMemorySize, FL_SMEM);
        cudaFuncSetAttribute(pair_mma,  cudaFuncAttributeMaxDynamicSharedMemorySize, PB_SMEM);
        init_done = 1;
    }

    a_stats_kernel<<<NTOK, 256>>>(a);
    prep_kernel<<<1, 128>>>(gz, bz, wz);
    pair_mma<<<dim3(NTOK / 128, NTOK), 256, PB_SMEM>>>(z, mask);

    float qscale = 1.0f / sqrtf((float)HD);
    qkvg_mma<<<dim3(CQ / 64, NTOK / 128, 4), 256>>>(a, ga, ba, wq, wk, wv, wg, bg, qscale);

    flash_mma<<<dim3(NTOK / 64, NH / 2), 256, FL_SMEM>>>();

    out_mma<<<dim3(CQ / 64, NTOK / 128), 256>>>(p_og, wo, out, bo);
}

// round 14
// speedup vs baseline: 1.0783x; 1.0783x over previous
#include <cuda_runtime.h>
#include <cuda_bf16.h>
#include <cuda_fp16.h>
#include <math.h>

#define NTOK 1024
#define CQ   768
#define CZ   128
#define NH   16
#define HD   48

// ---------------- scratch (static device memory) ----------------
__device__ float g_q   [NTOK * CQ];
__device__ float g_k   [NTOK * CQ];
__device__ float g_v   [NTOK * CQ];
__device__ float g_gate[NTOK * CQ];
__device__ float g_og  [NTOK * CQ];
__device__ __half g_sc [(size_t)NTOK * NH * NTOK];   // pair+mask bias (half), layout [i][h][j]
__device__ float g_wp  [CZ * NH];
__device__ float g_wpT [NH * 132];
__device__ float g_Wh  [NH];
__device__ float g_ch  [NH];
__device__ float g_mu  [NTOK];
__device__ float g_rs  [NTOK];

// ---------------- helpers ----------------
__device__ __forceinline__ unsigned f2tf(float x) {
    unsigned u; asm("cvt.rna.tf32.f32 %0, %1;" : "=r"(u) : "f"(x)); return u;
}
__device__ __forceinline__ float tf32f(float x) { return __uint_as_float(f2tf(x)); }
__device__ __forceinline__ unsigned su(float x) { return __float_as_uint(x); }

// pack (even k -> low half, odd k -> high half), hi/lo bf16 split
__device__ __forceinline__ void bfsplit2(float e, float o, unsigned& hw, unsigned& lw) {
    __nv_bfloat162 h2, l2;
    h2.x = __float2bfloat16_rn(e);
    h2.y = __float2bfloat16_rn(o);
    l2.x = __float2bfloat16_rn(e - __bfloat162float(h2.x));
    l2.y = __float2bfloat16_rn(o - __bfloat162float(h2.y));
    hw = *(unsigned*)&h2;
    lw = *(unsigned*)&l2;
}

#define MMA_TF32(c, a, b0_, b1_)                                              \
    asm volatile("mma.sync.aligned.m16n8k8.row.col.f32.tf32.tf32.f32 "        \
                 "{%0,%1,%2,%3}, {%4,%5,%6,%7}, {%8,%9}, {%0,%1,%2,%3};"      \
                 : "+f"(c[0]), "+f"(c[1]), "+f"(c[2]), "+f"(c[3])             \
                 : "r"(a[0]), "r"(a[1]), "r"(a[2]), "r"(a[3]),                \
                   "r"(b0_), "r"(b1_));

#define MMA_BF16(c, a, b0_, b1_)                                              \
    asm volatile("mma.sync.aligned.m16n8k16.row.col.f32.bf16.bf16.f32 "       \
                 "{%0,%1,%2,%3}, {%4,%5,%6,%7}, {%8,%9}, {%0,%1,%2,%3};"      \
                 : "+f"(c[0]), "+f"(c[1]), "+f"(c[2]), "+f"(c[3])             \
                 : "r"(a[0]), "r"(a[1]), "r"(a[2]), "r"(a[3]),                \
                   "r"(b0_), "r"(b1_));

// ---------------- per-row LN stats of a ----------------
__global__ void __launch_bounds__(256) a_stats_kernel(const float* __restrict__ a) {
    int row = blockIdx.x;
    int tid = threadIdx.x;
    const float* x = a + (size_t)row * CQ;
    __shared__ float red[256];

    float xv[3];
    float s = 0.f;
#pragma unroll
    for (int k = 0; k < 3; k++) { xv[k] = x[tid + k * 256]; s += xv[k]; }
    red[tid] = s; __syncthreads();
    for (int st = 128; st > 0; st >>= 1) { if (tid < st) red[tid] += red[tid + st]; __syncthreads(); }
    float mu = red[0] * (1.f / CQ);
    __syncthreads();

    float s2 = 0.f;
#pragma unroll
    for (int k = 0; k < 3; k++) { float d = xv[k] - mu; s2 += d * d; }
    red[tid] = s2; __syncthreads();
    for (int st = 128; st > 0; st >>= 1) { if (tid < st) red[tid] += red[tid + st]; __syncthreads(); }
    if (tid == 0) {
        g_mu[row] = mu;
        g_rs[row] = rsqrtf(red[0] * (1.f / CQ) + 1e-5f);
    }
}

// ---------------- pair-bias precompute ----------------
__global__ void prep_kernel(const float* __restrict__ gz,
                            const float* __restrict__ bz,
                            const float* __restrict__ wz) {
    int tid = threadIdx.x;       // 128
    float gzc = gz[tid];
    for (int h = 0; h < NH; h++) {
        float w = gzc * wz[tid * NH + h];
        g_wp[tid * NH + h] = w;
        g_wpT[h * 132 + tid] = tf32f(w);
    }
    __syncthreads();
    if (tid < NH) {
        float W = 0.f, C = 0.f;
        for (int c = 0; c < CZ; c++) {
            W += g_wp[c * NH + tid];
            C += bz[c] * wz[c * NH + tid];
        }
        g_Wh[tid] = W;
        g_ch[tid] = C;
    }
}

// ---------------- pair bias via tensor cores (half output) ----------------
__global__ void __launch_bounds__(256) pair_mma(const float* __restrict__ z,
                                                const float* __restrict__ mask) {
    extern __shared__ float psm[];
    float* zs  = psm;                     // 128*132
    float* wpt = zs + 128 * 132;          // 16*132
    float* sb  = wpt + 16 * 132;          // 16*132
    float* mus = sb + 16 * 132;           // 128
    float* rss = mus + 128;               // 128

    int i  = blockIdx.y;
    int j0 = blockIdx.x * 128;
    int tid = threadIdx.x, lane = tid & 31, w = tid >> 5;
    int g = lane >> 2, t = lane & 3;

    for (int e = tid; e < NH * 132; e += 256) wpt[e] = g_wpT[e];

    int row = tid >> 1, c0 = (tid & 1) * 64;
    const float* zrow = z + ((size_t)i * NTOK + j0 + row) * CZ + c0;
    float s1 = 0.f, s2 = 0.f;
#pragma unroll
    for (int q = 0; q < 16; q++) {
        float4 v = *(const float4*)&zrow[q * 4];
        s1 += v.x + v.y + v.z + v.w;
        s2 += v.x * v.x + v.y * v.y + v.z * v.z + v.w * v.w;
        float4 hv = make_float4(tf32f(v.x), tf32f(v.y), tf32f(v.z), tf32f(v.w));
        *(float4*)&zs[row * 132 + c0 + q * 4] = hv;
    }
    s1 += __shfl_xor_sync(0xffffffffu, s1, 1);
    s2 += __shfl_xor_sync(0xffffffffu, s2, 1);
    float mu = s1 * (1.f / CZ);
    float var = s2 * (1.f / CZ) - mu * mu;
    float rs = rsqrtf(var + 1e-5f);
    if ((tid & 1) == 0) { mus[row] = mu; rss[row] = rs; }
    __syncthreads();

    int wr = w * 16;
    float c[2][4] = {};
#pragma unroll
    for (int ks = 0; ks < 16; ks++) {
        int kk = ks * 8;
        unsigned a[4];
        a[0] = su(zs[(wr + g) * 132 + kk + t]);
        a[1] = su(zs[(wr + g + 8) * 132 + kk + t]);
        a[2] = su(zs[(wr + g) * 132 + kk + t + 4]);
        a[3] = su(zs[(wr + g + 8) * 132 + kk + t + 4]);
#pragma unroll
        for (int nt = 0; nt < 2; nt++) {
            unsigned b0 = su(wpt[(nt * 8 + g) * 132 + kk + t]);
            unsigned b1 = su(wpt[(nt * 8 + g) * 132 + kk + t + 4]);
            MMA_TF32(c[nt], a, b0, b1);
        }
    }

    float muA = mus[wr + g], rsA = rss[wr + g];
    float muB = mus[wr + g + 8], rsB = rss[wr + g + 8];
#pragma unroll
    for (int nt = 0; nt < 2; nt++) {
#pragma unroll
        for (int cc = 0; cc < 2; cc++) {
            int h = nt * 8 + 2 * t + cc;
            float W = g_Wh[h], C0 = g_ch[h];
            sb[h * 132 + wr + g]     = rsA * (c[nt][cc]     - muA * W) + C0;
            sb[h * 132 + wr + g + 8] = rsB * (c[nt][cc + 2] - muB * W) + C0;
        }
    }
    __syncthreads();

    float mi = mask[i];
#pragma unroll
    for (int e = tid; e < NH * 64; e += 256) {
        int h = e >> 6, jp = e & 63;
        int j = 2 * jp;
        float mb0 = fmaxf(-30000.f, 1.0e9f * (mi * mask[j0 + j]     - 1.f));
        float mb1 = fmaxf(-30000.f, 1.0e9f * (mi * mask[j0 + j + 1] - 1.f));
        __half2 hv = __floats2half2_rn(sb[h * 132 + j] + mb0, sb[h * 132 + j + 1] + mb1);
        *(__half2*)&g_sc[((size_t)i * NH + h) * NTOK + j0 + j] = hv;
    }
}

// ================= 3xBF16-split GEMM, 128x64 tile, BK=16 (round-12 proven core) =================
// packed bf16x2 smem: sAh/sAl [8][136] words, sBh/sBl [8][72] words
template <int LN_A>
__device__ __forceinline__ void gemm_core_bf(const float* __restrict__ A,
                                             const float* __restrict__ B,
                                             const float* __restrict__ gw,
                                             const float* __restrict__ bw,
                                             float c[2][4][4],
                                             unsigned* sAh, unsigned* sAl,
                                             unsigned* sBh, unsigned* sBl) {
    int tid  = threadIdx.x;
    int lane = tid & 31, w = tid >> 5;
    int wm = w & 3, wn = w >> 2;
    int g = lane >> 2, t = lane & 3;
    int m0 = blockIdx.y * 128, n0 = blockIdx.x * 64;
    int arow = tid >> 1, akb = (tid & 1) * 8;
    int bp = tid >> 5, bn = lane * 2;    // k-pair 0..7, n 0..62 step 2

    float mu = 0.f, rs = 1.f;
    if (LN_A) { mu = g_mu[m0 + arow]; rs = g_rs[m0 + arow]; }
    const float* Arow = A + (size_t)(m0 + arow) * CQ;

    for (int k0 = 0; k0 < CQ; k0 += 16) {
        __syncthreads();
        // ---- A tile: 8 consecutive k per thread -> 4 packed words (hi,lo) ----
        {
            float4 v0 = *(const float4*)&Arow[k0 + akb];
            float4 v1 = *(const float4*)&Arow[k0 + akb + 4];
            float xs[8] = {v0.x, v0.y, v0.z, v0.w, v1.x, v1.y, v1.z, v1.w};
            if (LN_A) {
#pragma unroll
                for (int q = 0; q < 8; q++)
                    xs[q] = (xs[q] - mu) * rs * gw[k0 + akb + q] + bw[k0 + akb + q];
            }
#pragma unroll
            for (int q = 0; q < 4; q++) {
                unsigned hw, lw;
                bfsplit2(xs[2 * q], xs[2 * q + 1], hw, lw);
                int p = (akb >> 1) + q;
                sAh[p * 136 + arow] = hw;
                sAl[p * 136 + arow] = lw;
            }
        }
        // ---- B tile: thread loads 2 n for 2 consecutive k rows ----
        {
            const float* Bp = &B[(size_t)(k0 + 2 * bp) * CQ + n0 + bn];
            float2 r0 = *(const float2*)Bp;
            float2 r1 = *(const float2*)(Bp + CQ);
            unsigned hw0, lw0, hw1, lw1;
            bfsplit2(r0.x, r1.x, hw0, lw0);
            bfsplit2(r0.y, r1.y, hw1, lw1);
            *(uint2*)&sBh[bp * 72 + bn] = make_uint2(hw0, hw1);
            *(uint2*)&sBl[bp * 72 + bn] = make_uint2(lw0, lw1);
        }
        __syncthreads();

        // ---- fragments + mma: ONE m16n8k16 step covers the 16-k chunk ----
        unsigned Ah[2][4], Al[2][4], Bh[4][2], Bl[4][2];
#pragma unroll
        for (int mt = 0; mt < 2; mt++) {
            int mb = wm * 32 + mt * 16 + g;
            Ah[mt][0] = sAh[t * 136 + mb];
            Ah[mt][1] = sAh[t * 136 + mb + 8];
            Ah[mt][2] = sAh[(t + 4) * 136 + mb];
            Ah[mt][3] = sAh[(t + 4) * 136 + mb + 8];
            Al[mt][0] = sAl[t * 136 + mb];
            Al[mt][1] = sAl[t * 136 + mb + 8];
            Al[mt][2] = sAl[(t + 4) * 136 + mb];
            Al[mt][3] = sAl[(t + 4) * 136 + mb + 8];
        }
#pragma unroll
        for (int nt = 0; nt < 4; nt++) {
            int nb = wn * 32 + nt * 8 + g;
            Bh[nt][0] = sBh[t * 72 + nb];
            Bh[nt][1] = sBh[(t + 4) * 72 + nb];
            Bl[nt][0] = sBl[t * 72 + nb];
            Bl[nt][1] = sBl[(t + 4) * 72 + nb];
        }
#pragma unroll
        for (int mt = 0; mt < 2; mt++)
#pragma unroll
            for (int nt = 0; nt < 4; nt++) {
                MMA_BF16(c[mt][nt], Ah[mt], Bh[nt][0], Bh[nt][1]);
                MMA_BF16(c[mt][nt], Ah[mt], Bl[nt][0], Bl[nt][1]);
                MMA_BF16(c[mt][nt], Al[mt], Bh[nt][0], Bh[nt][1]);
            }
    }
}

#define GEMM_BF_SMEM                                                          \
    __shared__ unsigned sAh[8 * 136], sAl[8 * 136];                           \
    __shared__ unsigned sBh[8 * 72],  sBl[8 * 72];

// fused Q/K/V/Gate projections (LN applied to A on the fly)
__global__ void __launch_bounds__(256) qkvg_mma(const float* __restrict__ A,
                                                const float* __restrict__ gw,
                                                const float* __restrict__ bw,
                                                const float* __restrict__ wq,
                                                const float* __restrict__ wk,
                                                const float* __restrict__ wv,
                                                const float* __restrict__ wg,
                                                const float* __restrict__ bg,
                                                float qscale) {
    GEMM_BF_SMEM
    int zi = blockIdx.z;
    const float* B = (zi == 0) ? wq : (zi == 1) ? wk : (zi == 2) ? wv : wg;
    float* O = (zi == 0) ? g_q : (zi == 1) ? g_k : (zi == 2) ? g_v : g_gate;

    float c[2][4][4] = {};
    gemm_core_bf<1>(A, B, gw, bw, c, sAh, sAl, sBh, sBl);

    int lane = threadIdx.x & 31, w = threadIdx.x >> 5;
    int wm = w & 3, wn = w >> 2;
    int g = lane >> 2, t = lane & 3;
    int m0 = blockIdx.y * 128, n0 = blockIdx.x * 64;
#pragma unroll
    for (int mt = 0; mt < 2; mt++) {
        int r0 = m0 + wm * 32 + mt * 16 + g;
#pragma unroll
        for (int nt = 0; nt < 4; nt++) {
            int col = n0 + wn * 32 + nt * 8 + 2 * t;
            float v0 = c[mt][nt][0], v1 = c[mt][nt][1];
            float v2 = c[mt][nt][2], v3 = c[mt][nt][3];
            if (zi == 0) { v0 *= qscale; v1 *= qscale; v2 *= qscale; v3 *= qscale; }
            if (zi == 3) {
                float2 bb = *(const float2*)&bg[col];
                v0 = 1.f / (1.f + __expf(-(v0 + bb.x)));
                v1 = 1.f / (1.f + __expf(-(v1 + bb.y)));
                v2 = 1.f / (1.f + __expf(-(v2 + bb.x)));
                v3 = 1.f / (1.f + __expf(-(v3 + bb.y)));
            }
            *(float2*)&O[(size_t)r0 * CQ + col]       = make_float2(v0, v1);
            *(float2*)&O[(size_t)(r0 + 8) * CQ + col] = make_float2(v2, v3);
        }
    }
}

// out projection
__global__ void __launch_bounds__(256) out_mma(const float* __restrict__ A,
                                               const float* __restrict__ B,
                                               float* __restrict__ C,
                                               const float* __restrict__ bias) {
    GEMM_BF_SMEM
    float c[2][4][4] = {};
    gemm_core_bf<0>(A, B, (const float*)0, (const float*)0, c, sAh, sAl, sBh, sBl);

    int lane = threadIdx.x & 31, w = threadIdx.x >> 5;
    int wm = w & 3, wn = w >> 2;
    int g = lane >> 2, t = lane & 3;
    int m0 = blockIdx.y * 128, n0 = blockIdx.x * 64;
#pragma unroll
    for (int mt = 0; mt < 2; mt++) {
        int r0 = m0 + wm * 32 + mt * 16 + g;
#pragma unroll
        for (int nt = 0; nt < 4; nt++) {
            int col = n0 + wn * 32 + nt * 8 + 2 * t;
            float2 bb = *(const float2*)&bias[col];
            *(float2*)&C[(size_t)r0 * CQ + col] =
                make_float2(c[mt][nt][0] + bb.x, c[mt][nt][1] + bb.y);
            *(float2*)&C[(size_t)(r0 + 8) * CQ + col] =
                make_float2(c[mt][nt][2] + bb.x, c[mt][nt][3] + bb.y);
        }
    }
}

// ================= flash attention: 64 q-rows x 2 heads per block, 256 thr =================
// smem: Ks[2][64*68] | Vs[2][64*72] | Ps[8][16*68]; bias (half) loaded direct to fragments
__global__ void __launch_bounds__(256) flash_mma() {
    extern __shared__ float fsm[];

    int tid = threadIdx.x, w = tid >> 5, lane = tid & 31;
    int hh = w >> 2, wl = w & 3;
    int g = lane >> 2, t = lane & 3;

    float* Ks = fsm + hh * 4352;
    float* Vs = fsm + 8704 + hh * 4608;
    float* Pw = fsm + 8704 + 9216 + w * 1088;

    int h  = blockIdx.y * 2 + hh;
    int i0 = blockIdx.x * 64;
    int irow = i0 + wl * 16 + g;

    unsigned aq[6][4];
    {
        const float* q0 = g_q + (size_t)irow * CQ + h * HD;
        const float* q8 = q0 + 8 * CQ;
#pragma unroll
        for (int ks = 0; ks < 6; ks++) {
            aq[ks][0] = f2tf(q0[ks * 8 + t]);
            aq[ks][1] = f2tf(q8[ks * 8 + t]);
            aq[ks][2] = f2tf(q0[ks * 8 + t + 4]);
            aq[ks][3] = f2tf(q8[ks * 8 + t + 4]);
        }
    }

    const __half* scA = g_sc + ((size_t)irow * NH + h) * NTOK;
    const __half* scB = scA + (size_t)8 * NH * NTOK;

    float o[6][4] = {};
    float mrunA = -1e30f, mrunB = -1e30f, lA = 0.f, lB = 0.f;

    for (int jt = 0; jt < 16; jt++) {
        int j0 = jt * 64;
        __syncthreads();

        float s[8][4];
#pragma unroll
        for (int nt = 0; nt < 8; nt++) {
            float2 bA = __half22float2(*(const __half2*)&scA[j0 + nt * 8 + 2 * t]);
            float2 bB = __half22float2(*(const __half2*)&scB[j0 + nt * 8 + 2 * t]);
            s[nt][0] = bA.x; s[nt][1] = bA.y; s[nt][2] = bB.x; s[nt][3] = bB.y;
        }

#pragma unroll
        for (int e = tid; e < 1536; e += 256) {
            int hd2 = (e >= 768);
            int e2 = e - hd2 * 768;
            int r = e2 / 12, cc = (e2 % 12) * 4;
            int hl = blockIdx.y * 2 + hd2;
            float* Kd = fsm + hd2 * 4352;
            float* Vd = fsm + 8704 + hd2 * 4608;
            float4 kv = *(const float4*)&g_k[(size_t)(j0 + r) * CQ + hl * HD + cc];
            Kd[r * 68 + cc + 0] = tf32f(kv.x); Kd[r * 68 + cc + 1] = tf32f(kv.y);
            Kd[r * 68 + cc + 2] = tf32f(kv.z); Kd[r * 68 + cc + 3] = tf32f(kv.w);
            float4 vv = *(const float4*)&g_v[(size_t)(j0 + r) * CQ + hl * HD + cc];
            Vd[r * 72 + cc + 0] = tf32f(vv.x); Vd[r * 72 + cc + 1] = tf32f(vv.y);
            Vd[r * 72 + cc + 2] = tf32f(vv.z); Vd[r * 72 + cc + 3] = tf32f(vv.w);
        }
        __syncthreads();

#pragma unroll
        for (int ks = 0; ks < 6; ks++) {
#pragma unroll
            for (int nt = 0; nt < 8; nt++) {
                unsigned b0 = su(Ks[(nt * 8 + g) * 68 + ks * 8 + t]);
                unsigned b1 = su(Ks[(nt * 8 + g) * 68 + ks * 8 + t + 4]);
                MMA_TF32(s[nt], aq[ks], b0, b1);
            }
        }

        float mA = -1e30f, mB = -1e30f;
#pragma unroll
        for (int nt = 0; nt < 8; nt++) {
            mA = fmaxf(mA, fmaxf(s[nt][0], s[nt][1]));
            mB = fmaxf(mB, fmaxf(s[nt][2], s[nt][3]));
        }
#pragma unroll
        for (int oo = 1; oo <= 2; oo <<= 1) {
            mA = fmaxf(mA, __shfl_xor_sync(0xffffffffu, mA, oo));
            mB = fmaxf(mB, __shfl_xor_sync(0xffffffffu, mB, oo));
        }
        float mnA = fmaxf(mrunA, mA), mnB = fmaxf(mrunB, mB);
        float alA = __expf(mrunA - mnA), alB = __expf(mrunB - mnB);
        mrunA = mnA; mrunB = mnB;

        float sumA = 0.f, sumB = 0.f;
#pragma unroll
        for (int nt = 0; nt < 8; nt++) {
            s[nt][0] = __expf(s[nt][0] - mnA); s[nt][1] = __expf(s[nt][1] - mnA);
            s[nt][2] = __expf(s[nt][2] - mnB); s[nt][3] = __expf(s[nt][3] - mnB);
            sumA += s[nt][0] + s[nt][1];
            sumB += s[nt][2] + s[nt][3];
        }
#pragma unroll
        for (int oo = 1; oo <= 2; oo <<= 1) {
            sumA += __shfl_xor_sync(0xffffffffu, sumA, oo);
            sumB += __shfl_xor_sync(0xffffffffu, sumB, oo);
        }
        lA = lA * alA + sumA;
        lB = lB * alB + sumB;
#pragma unroll
        for (int nd = 0; nd < 6; nd++) {
            o[nd][0] *= alA; o[nd][1] *= alA;
            o[nd][2] *= alB; o[nd][3] *= alB;
        }

#pragma unroll
        for (int nt = 0; nt < 8; nt++) {
            *(float2*)&Pw[g * 68 + nt * 8 + 2 * t]       = make_float2(tf32f(s[nt][0]), tf32f(s[nt][1]));
            *(float2*)&Pw[(g + 8) * 68 + nt * 8 + 2 * t] = make_float2(tf32f(s[nt][2]), tf32f(s[nt][3]));
        }
        __syncwarp();

#pragma unroll
        for (int ks = 0; ks < 8; ks++) {
            unsigned pa[4];
            pa[0] = su(Pw[g * 68 + ks * 8 + t]);
            pa[1] = su(Pw[(g + 8) * 68 + ks * 8 + t]);
            pa[2] = su(Pw[g * 68 + ks * 8 + t + 4]);
            pa[3] = su(Pw[(g + 8) * 68 + ks * 8 + t + 4]);
#pragma unroll
            for (int nd = 0; nd < 6; nd++) {
                unsigned b0 = su(Vs[(ks * 8 + t) * 72 + nd * 8 + g]);
                unsigned b1 = su(Vs[(ks * 8 + t + 4) * 72 + nd * 8 + g]);
                MMA_TF32(o[nd], pa, b0, b1);
            }
        }
    }

    float iA = 1.f / lA, iB = 1.f / lB;
#pragma unroll
    for (int nd = 0; nd < 6; nd++) {
        int col = h * HD + nd * 8 + 2 * t;
        size_t iAx = (size_t)irow * CQ + col;
        size_t iBx = (size_t)(irow + 8) * CQ + col;
        float2 ga = *(const float2*)&g_gate[iAx];
        float2 gb = *(const float2*)&g_gate[iBx];
        *(float2*)&g_og[iAx] = make_float2(o[nd][0] * iA * ga.x, o[nd][1] * iA * ga.y);
        *(float2*)&g_og[iBx] = make_float2(o[nd][2] * iB * gb.x, o[nd][3] * iB * gb.y);
    }
}

// ------------------------------- launch -------------------------------
#define PB_SMEM ((128 * 132 + 16 * 132 + 16 * 132 + 256) * 4)
#define FL_SMEM ((2 * 4352 + 2 * 4608 + 8 * 1088) * 4)

extern "C" void kernel_launch(void* const* d_in, const int* in_sizes, int n_in,
                              void* d_out, int out_size) {
    const float* a    = (const float*)d_in[0];
    const float* z    = (const float*)d_in[1];
    const float* mask = (const float*)d_in[2];
    const float* ga   = (const float*)d_in[3];
    const float* ba   = (const float*)d_in[4];
    const float* gz   = (const float*)d_in[5];
    const float* bz   = (const float*)d_in[6];
    const float* wz   = (const float*)d_in[7];
    const float* wq   = (const float*)d_in[8];
    const float* wk   = (const float*)d_in[9];
    const float* wv   = (const float*)d_in[10];
    const float* wg   = (const float*)d_in[11];
    const float* bg   = (const float*)d_in[12];
    const float* wo   = (const float*)d_in[13];
    const float* bo   = (const float*)d_in[14];
    float* out = (float*)d_out;

    float *p_og;
    cudaGetSymbolAddress((void**)&p_og, g_og);

    static int init_done = 0;
    if (!init_done) {
        cudaFuncSetAttribute(flash_mma, cudaFuncAttributeMaxDynamicSharedMemorySize, FL_SMEM);
        cudaFuncSetAttribute(pair_mma,  cudaFuncAttributeMaxDynamicSharedMemorySize, PB_SMEM);
        init_done = 1;
    }

    a_stats_kernel<<<NTOK, 256>>>(a);
    prep_kernel<<<1, 128>>>(gz, bz, wz);
    pair_mma<<<dim3(NTOK / 128, NTOK), 256, PB_SMEM>>>(z, mask);

    float qscale = 1.0f / sqrtf((float)HD);
    qkvg_mma<<<dim3(CQ / 64, NTOK / 128, 4), 256>>>(a, ga, ba, wq, wk, wv, wg, bg, qscale);

    flash_mma<<<dim3(NTOK / 64, NH / 2), 256, FL_SMEM>>>();

    out_mma<<<dim3(CQ / 64, NTOK / 128), 256>>>(p_og, wo, out, bo);
}